// round 14
// baseline (speedup 1.0000x reference)
#include <cuda_runtime.h>
#include <cuda_fp16.h>
#include <cstdint>

#define T_TOK 16384
#define HID   2048
#define IEXP  1024
#define NEXP  8
#define VOCAB_SZ 100000
#define TPE   12500

#define BM 256
#define BK 32
#define STRA 40                         // 80B/row: 16B-aligned, ldmatrix conflict-free
#define AH (BM * STRA)                  // 10240 halfs / stage

#define BSTRF 72
#define BHF (2 * BK * BSTRF)            // 4608 halfs
#define STGH_F (AH + BHF)               // 14848 halfs = 29696 B
#define NST 5
#define SMB_F (NST * STGH_F * 2 + 1088) // ~149.5 KB

#define BSTRD 136
#define BHD (BK * BSTRD)                // 4352 halfs
#define STGH_D (AH + BHD)               // 14592 halfs
#define SMB_D (NST * STGH_D * 2 + 1088)

__device__ __half x_h [(size_t)T_TOK * HID];
__device__ __half h_h [(size_t)T_TOK * IEXP];
__device__ __half gw_h[(size_t)NEXP * HID * IEXP];
__device__ __half uw_h[(size_t)NEXP * HID * IEXP];
__device__ __half dw_h[(size_t)NEXP * IEXP * HID];
__device__ int    perm_d[T_TOK];
__device__ int    cnt_d[NEXP];
__device__ int    base_d[NEXP];

__global__ void k_route(const int* __restrict__ ids) {
    __shared__ int c[NEXP], b[NEXP], cu[NEXP];
    int t = threadIdx.x;
    if (t < NEXP) { c[t] = 0; cu[t] = 0; }
    __syncthreads();
    for (int i = t; i < T_TOK; i += 256) {
        int v = ids[i]; v = max(0, min(v, VOCAB_SZ - 1));
        atomicAdd(&c[min(v / TPE, NEXP - 1)], 1);
    }
    __syncthreads();
    if (t == 0) { int s = 0; for (int e = 0; e < NEXP; e++) { b[e] = s; s += c[e]; } }
    __syncthreads();
    for (int i = t; i < T_TOK; i += 256) {
        int v = ids[i]; v = max(0, min(v, VOCAB_SZ - 1));
        int e = min(v / TPE, NEXP - 1);
        perm_d[b[e] + atomicAdd(&cu[e], 1)] = i;
    }
    if (t < NEXP) { cnt_d[t] = c[t]; base_d[t] = b[t]; }
}

__global__ void k_prep(const float* __restrict__ X) {
    size_t i = ((size_t)blockIdx.x * blockDim.x + threadIdx.x) * 8;
    float4 v0 = *(const float4*)(X + i);
    float4 v1 = *(const float4*)(X + i + 4);
    __half2 h0 = __floats2half2_rn(v0.x, v0.y), h1 = __floats2half2_rn(v0.z, v0.w);
    __half2 h2 = __floats2half2_rn(v1.x, v1.y), h3 = __floats2half2_rn(v1.z, v1.w);
    uint4 w = make_uint4(*(unsigned*)&h0, *(unsigned*)&h1, *(unsigned*)&h2, *(unsigned*)&h3);
    *(uint4*)(x_h + i) = w;
}

__global__ void k_wconv(const float* __restrict__ G, const float* __restrict__ U,
                        const float* __restrict__ D) {
    const float* src = (blockIdx.y == 0) ? G : (blockIdx.y == 1) ? U : D;
    __half* dst = (blockIdx.y == 0) ? gw_h : (blockIdx.y == 1) ? uw_h : dw_h;
    size_t i = ((size_t)blockIdx.x * blockDim.x + threadIdx.x) * 8;
    float4 v0 = *(const float4*)(src + i);
    float4 v1 = *(const float4*)(src + i + 4);
    __half2 h0 = __floats2half2_rn(v0.x, v0.y), h1 = __floats2half2_rn(v0.z, v0.w);
    __half2 h2 = __floats2half2_rn(v1.x, v1.y), h3 = __floats2half2_rn(v1.z, v1.w);
    uint4 w = make_uint4(*(unsigned*)&h0, *(unsigned*)&h1, *(unsigned*)&h2, *(unsigned*)&h3);
    *(uint4*)(dst + i) = w;
}

__device__ __forceinline__ void mma_h(float* c, const unsigned* a, const unsigned* b) {
    asm volatile(
        "mma.sync.aligned.m16n8k16.row.col.f32.f16.f16.f32 "
        "{%0,%1,%2,%3},{%4,%5,%6,%7},{%8,%9},{%0,%1,%2,%3};"
        : "+f"(c[0]), "+f"(c[1]), "+f"(c[2]), "+f"(c[3])
        : "r"(a[0]), "r"(a[1]), "r"(a[2]), "r"(a[3]), "r"(b[0]), "r"(b[1]));
}
__device__ __forceinline__ void cp16(unsigned dst, const void* src) {
    asm volatile("cp.async.cg.shared.global [%0], [%1], 16;" :: "r"(dst), "l"(src));
}
#define CP_COMMIT() asm volatile("cp.async.commit_group;")
#define CP_WAIT3()  asm volatile("cp.async.wait_group 3;")
#define LDSM4(r0, r1, r2, r3, addr)                                             \
    asm volatile("ldmatrix.sync.aligned.m8n8.x4.shared.b16 {%0,%1,%2,%3}, [%4];" \
        : "=r"(r0), "=r"(r1), "=r"(r2), "=r"(r3) : "r"(addr))
#define LDSM4T(r0, r1, r2, r3, addr)                                            \
    asm volatile("ldmatrix.sync.aligned.m8n8.x4.trans.shared.b16 {%0,%1,%2,%3}, [%4];" \
        : "=r"(r0), "=r"(r1), "=r"(r2), "=r"(r3) : "r"(addr))

// ============== fused gate/up + silu: CTA 256m x 64n (both matrices) =========
__global__ __launch_bounds__(512, 1)
void k_mlp()
{
    extern __shared__ __half smh[];
    int e   = blockIdx.z;
    int cnt = cnt_d[e];
    int m0  = blockIdx.y * BM;
    if (m0 >= cnt) return;
    int n0    = blockIdx.x * 64;
    int valid = min(cnt - m0, BM);
    int pbase = base_d[e] + m0;
    int tid = threadIdx.x, lane = tid & 31, wid = tid >> 5;

    int* toks = (int*)(smh + NST * STGH_F);
    if (tid < BM) toks[tid] = perm_d[pbase + min(tid, valid - 1)];
    __syncthreads();

    // A: 2 thr/row, 16 halfs (2 cp16) each -> 256 rows x 32 halfs
    int arow = tid >> 1, aseg = tid & 1;
    const __half* Ag = x_h + (size_t)toks[arow] * HID + aseg * 16;
    unsigned sb = (unsigned)__cvta_generic_to_shared(smh);
    unsigned aD = sb + (arow * STRA + aseg * 16) * 2;

    // B: 2 mat x 32 k-rows x 64 halfs; 1 cp16/thread
    int bmat = tid >> 8, brw = (tid & 255) >> 3, bsg = tid & 7;
    const __half* Bg = (bmat ? uw_h : gw_h) + (size_t)e * HID * IEXP
                     + (size_t)brw * IEXP + n0 + bsg * 8;
    unsigned bD = sb + (AH + bmat * (BK * BSTRF) + brw * BSTRF + bsg * 8) * 2;

    auto stage = [&](int s, int k0) {
        unsigned off = (unsigned)s * (STGH_F * 2);
        const __half* as = Ag + k0;
        cp16(aD + off,      as);
        cp16(aD + off + 16, as + 8);
        cp16(bD + off, Bg + (size_t)k0 * IEXP);
    };

    float acc[2][8][4];
#pragma unroll
    for (int i = 0; i < 2; i++)
#pragma unroll
        for (int j = 0; j < 8; j++)
#pragma unroll
            for (int k = 0; k < 4; k++) acc[i][j][k] = 0.f;

    int sel = wid >> 3;                   // 0: gate (warps 0-7), 1: up (warps 8-15)
    int wm  = (wid & 7) * 32;             // 8 M-positions x 32 = 256

    unsigned aLd = sb + ((wm + (lane & 7) + ((lane >> 3) & 1) * 8) * STRA
                         + ((lane >> 4) & 1) * 8) * 2;
    unsigned bLd = sb + (AH + sel * (BK * BSTRF)
                         + ((lane & 7) + ((lane >> 3) & 1) * 8) * BSTRF
                         + ((lane >> 4) & 1) * 8) * 2;

    stage(0, 0);      CP_COMMIT();
    stage(1, BK);     CP_COMMIT();
    stage(2, 2 * BK); CP_COMMIT();
    stage(3, 3 * BK); CP_COMMIT();

    const int nch = HID / BK;             // 64
    int s = 0;
    for (int i = 0; i < nch; i++) {
        CP_WAIT3();
        __syncthreads();
        {
            int s4 = s + 4; if (s4 >= NST) s4 -= NST;
            if (i + 4 < nch) stage(s4, (i + 4) * BK);
        }
        CP_COMMIT();

        unsigned stOff = (unsigned)s * (STGH_F * 2);
#pragma unroll
        for (int kk = 0; kk < 2; kk++) {
            unsigned af[2][4];
#pragma unroll
            for (int mi = 0; mi < 2; mi++)
                LDSM4(af[mi][0], af[mi][1], af[mi][2], af[mi][3],
                      aLd + stOff + mi * (16 * STRA * 2) + kk * 32);
#pragma unroll
            for (int p = 0; p < 4; p++) {
                unsigned b0, b1, b2, b3;
                LDSM4T(b0, b1, b2, b3,
                       bLd + stOff + kk * (16 * BSTRF * 2) + p * 32);
                unsigned bf0[2] = { b0, b1 }, bf1[2] = { b2, b3 };
#pragma unroll
                for (int mi = 0; mi < 2; mi++) {
                    mma_h(acc[mi][2 * p],     af[mi], bf0);
                    mma_h(acc[mi][2 * p + 1], af[mi], bf1);
                }
            }
        }
        s = (s + 1 == NST) ? 0 : s + 1;
    }
    __syncthreads();

    // ---- exchange + silu ----
    float* HS = (float*)smh + sel * (BM * 68);   // 2 x 256x68 f32 = 139 KB
#pragma unroll
    for (int mi = 0; mi < 2; mi++) {
        int rb = wm + mi * 16 + (lane >> 2);
#pragma unroll
        for (int ni = 0; ni < 8; ni++) {
            int cc = ni * 8 + (lane & 3) * 2;
            HS[rb * 68 + cc]           = acc[mi][ni][0];
            HS[rb * 68 + cc + 1]       = acc[mi][ni][1];
            HS[(rb + 8) * 68 + cc]     = acc[mi][ni][2];
            HS[(rb + 8) * 68 + cc + 1] = acc[mi][ni][3];
        }
    }
    __syncthreads();
    {
        int r = tid >> 1, hf = tid & 1;
        if (r < valid) {
            const float* g = (float*)smh + r * 68 + hf * 32;
            const float* u = (float*)smh + BM * 68 + r * 68 + hf * 32;
            __half* dst = h_h + (size_t)(pbase + r) * IEXP + n0 + hf * 32;
#pragma unroll
            for (int j = 0; j < 32; j += 8) {
                float hv[8];
#pragma unroll
                for (int q = 0; q < 8; q++) {
                    float gv = g[j + q], uv = u[j + q];
                    hv[q] = gv / (1.f + __expf(-gv)) * uv;
                }
                __half2 p0 = __floats2half2_rn(hv[0], hv[1]);
                __half2 p1 = __floats2half2_rn(hv[2], hv[3]);
                __half2 p2 = __floats2half2_rn(hv[4], hv[5]);
                __half2 p3 = __floats2half2_rn(hv[6], hv[7]);
                uint4 w = make_uint4(*(unsigned*)&p0, *(unsigned*)&p1,
                                     *(unsigned*)&p2, *(unsigned*)&p3);
                *(uint4*)(dst + j) = w;
            }
        }
    }
}

// ============== down-proj: CTA 256m x 128n, row scatter ======================
__global__ __launch_bounds__(512, 1)
void k_down(float* __restrict__ out)
{
    extern __shared__ __half smh[];
    int e   = blockIdx.z;
    int cnt = cnt_d[e];
    int m0  = blockIdx.y * BM;
    if (m0 >= cnt) return;
    int n0    = blockIdx.x * 128;
    int valid = min(cnt - m0, BM);
    int pbase = base_d[e] + m0;
    int tid = threadIdx.x, lane = tid & 31, wid = tid >> 5;

    int* toks = (int*)(smh + NST * STGH_D);
    if (tid < BM) toks[tid] = perm_d[pbase + min(tid, valid - 1)];
    __syncthreads();

    int arow = tid >> 1, aseg = tid & 1;
    const __half* Ag = h_h + (size_t)(pbase + min(arow, valid - 1)) * IEXP + aseg * 16;
    unsigned sb = (unsigned)__cvta_generic_to_shared(smh);
    unsigned aD = sb + (arow * STRA + aseg * 16) * 2;

    // B: 32 k-rows x 128 halfs; 1 cp16/thread
    int brw = tid >> 4, bsg = tid & 15;
    const __half* Dg = dw_h + (size_t)e * IEXP * HID + (size_t)brw * HID + n0 + bsg * 8;
    unsigned bD = sb + (AH + brw * BSTRD + bsg * 8) * 2;

    auto stage = [&](int s, int k0) {
        unsigned off = (unsigned)s * (STGH_D * 2);
        const __half* as = Ag + k0;
        cp16(aD + off,      as);
        cp16(aD + off + 16, as + 8);
        cp16(bD + off, Dg + (size_t)k0 * HID);
    };

    float acc[2][8][4];
#pragma unroll
    for (int i = 0; i < 2; i++)
#pragma unroll
        for (int j = 0; j < 8; j++)
#pragma unroll
            for (int k = 0; k < 4; k++) acc[i][j][k] = 0.f;

    int wm = (wid & 7) * 32;              // 8 M-positions
    int wn = (wid >> 3) * 64;             // 2 N-positions

    unsigned aLd = sb + ((wm + (lane & 7) + ((lane >> 3) & 1) * 8) * STRA
                         + ((lane >> 4) & 1) * 8) * 2;
    unsigned bLd = sb + (AH + ((lane & 7) + ((lane >> 3) & 1) * 8) * BSTRD
                         + wn + ((lane >> 4) & 1) * 8) * 2;

    stage(0, 0);      CP_COMMIT();
    stage(1, BK);     CP_COMMIT();
    stage(2, 2 * BK); CP_COMMIT();
    stage(3, 3 * BK); CP_COMMIT();

    const int nch = IEXP / BK;            // 32
    int s = 0;
    for (int i = 0; i < nch; i++) {
        CP_WAIT3();
        __syncthreads();
        {
            int s4 = s + 4; if (s4 >= NST) s4 -= NST;
            if (i + 4 < nch) stage(s4, (i + 4) * BK);
        }
        CP_COMMIT();

        unsigned stOff = (unsigned)s * (STGH_D * 2);
#pragma unroll
        for (int kk = 0; kk < 2; kk++) {
            unsigned af[2][4];
#pragma unroll
            for (int mi = 0; mi < 2; mi++)
                LDSM4(af[mi][0], af[mi][1], af[mi][2], af[mi][3],
                      aLd + stOff + mi * (16 * STRA * 2) + kk * 32);
#pragma unroll
            for (int p = 0; p < 4; p++) {
                unsigned b0, b1, b2, b3;
                LDSM4T(b0, b1, b2, b3,
                       bLd + stOff + kk * (16 * BSTRD * 2) + p * 32);
                unsigned bf0[2] = { b0, b1 }, bf1[2] = { b2, b3 };
#pragma unroll
                for (int mi = 0; mi < 2; mi++) {
                    mma_h(acc[mi][2 * p],     af[mi], bf0);
                    mma_h(acc[mi][2 * p + 1], af[mi], bf1);
                }
            }
        }
        s = (s + 1 == NST) ? 0 : s + 1;
    }

#pragma unroll
    for (int mi = 0; mi < 2; mi++) {
        int rb = wm + mi * 16 + (lane >> 2);
#pragma unroll
        for (int ni = 0; ni < 8; ni++) {
            int cc = n0 + wn + ni * 8 + (lane & 3) * 2;
#pragma unroll
            for (int h = 0; h < 2; h++) {
                int r = rb + h * 8;
                if (r < valid) {
                    float* row = out + (size_t)toks[r] * HID;
                    row[cc]     = acc[mi][ni][h * 2];
                    row[cc + 1] = acc[mi][ni][h * 2 + 1];
                }
            }
        }
    }
}

extern "C" void kernel_launch(void* const* d_in, const int* in_sizes, int n_in,
                              void* d_out, int out_size)
{
    const float* hs   = (const float*)d_in[0];
    const int*   ids  = (const int*)d_in[1];
    const float* gate = (const float*)d_in[2];
    const float* up   = (const float*)d_in[3];
    const float* down = (const float*)d_in[4];
    float*       out  = (float*)d_out;

    cudaFuncSetAttribute(k_mlp,  cudaFuncAttributeMaxDynamicSharedMemorySize, SMB_F);
    cudaFuncSetAttribute(k_down, cudaFuncAttributeMaxDynamicSharedMemorySize, SMB_D);

    k_route<<<1, 256>>>(ids);
    k_prep<<<(T_TOK * HID) / 2048, 256>>>(hs);
    k_wconv<<<dim3((NEXP * HID * IEXP) / 2048, 3), 256>>>(gate, up, down);
    k_mlp <<<dim3(IEXP / 64,  T_TOK / BM, NEXP), 512, SMB_F>>>();
    k_down<<<dim3(HID / 128, T_TOK / BM, NEXP), 512, SMB_D>>>(out);
}

// round 15
// speedup vs baseline: 1.1107x; 1.1107x over previous
#include <cuda_runtime.h>
#include <cuda_fp16.h>
#include <cstdint>

#define T_TOK 16384
#define HID   2048
#define IEXP  1024
#define NEXP  8
#define VOCAB_SZ 100000
#define TPE   12500

#define BM 128
#define BK 32
#define STRA 40                          // 80B/row, 16B-aligned, conflict-free
#define AH (BM * STRA)                   // 5120 halfs
#define BSTR 264                         // 256n + 8 pad; 528B row, conflict-free for trans
#define BH (BK * BSTR)                   // 8448 halfs
#define STGH (AH + BH)                   // 13568 halfs = 27136 B / stage
#define NST 4

#define HSW 132                          // epilogue fp32 stride (floats)
#define HS_BYTES (2 * BM * HSW * 4)      // 135168 B
#define TOKS_OFF_F HS_BYTES              // fused: toks after HS region (> stages 108.5KB)
#define SMB_F (TOKS_OFF_F + 512 + 64)
#define TOKS_OFF_D (NST * STGH * 2)
#define SMB_D (TOKS_OFF_D + 512 + 64)

__device__ __half x_h [(size_t)T_TOK * HID];
__device__ __half h_h [(size_t)T_TOK * IEXP];
__device__ __half gw_h[(size_t)NEXP * HID * IEXP];
__device__ __half uw_h[(size_t)NEXP * HID * IEXP];
__device__ __half dw_h[(size_t)NEXP * IEXP * HID];
__device__ int    perm_d[T_TOK];
__device__ int    cnt_d[NEXP];
__device__ int    base_d[NEXP];

__global__ void k_route(const int* __restrict__ ids) {
    __shared__ int c[NEXP], b[NEXP], cu[NEXP];
    int t = threadIdx.x;
    if (t < NEXP) { c[t] = 0; cu[t] = 0; }
    __syncthreads();
    for (int i = t; i < T_TOK; i += 256) {
        int v = ids[i]; v = max(0, min(v, VOCAB_SZ - 1));
        atomicAdd(&c[min(v / TPE, NEXP - 1)], 1);
    }
    __syncthreads();
    if (t == 0) { int s = 0; for (int e = 0; e < NEXP; e++) { b[e] = s; s += c[e]; } }
    __syncthreads();
    for (int i = t; i < T_TOK; i += 256) {
        int v = ids[i]; v = max(0, min(v, VOCAB_SZ - 1));
        int e = min(v / TPE, NEXP - 1);
        perm_d[b[e] + atomicAdd(&cu[e], 1)] = i;
    }
    if (t < NEXP) { cnt_d[t] = c[t]; base_d[t] = b[t]; }
}

__global__ void k_prep(const float* __restrict__ X) {
    size_t i = ((size_t)blockIdx.x * blockDim.x + threadIdx.x) * 8;
    float4 v0 = *(const float4*)(X + i);
    float4 v1 = *(const float4*)(X + i + 4);
    __half2 h0 = __floats2half2_rn(v0.x, v0.y), h1 = __floats2half2_rn(v0.z, v0.w);
    __half2 h2 = __floats2half2_rn(v1.x, v1.y), h3 = __floats2half2_rn(v1.z, v1.w);
    uint4 w = make_uint4(*(unsigned*)&h0, *(unsigned*)&h1, *(unsigned*)&h2, *(unsigned*)&h3);
    *(uint4*)(x_h + i) = w;
}

__global__ void k_wconv(const float* __restrict__ G, const float* __restrict__ U,
                        const float* __restrict__ D) {
    const float* src = (blockIdx.y == 0) ? G : (blockIdx.y == 1) ? U : D;
    __half* dst = (blockIdx.y == 0) ? gw_h : (blockIdx.y == 1) ? uw_h : dw_h;
    size_t i = ((size_t)blockIdx.x * blockDim.x + threadIdx.x) * 8;
    float4 v0 = *(const float4*)(src + i);
    float4 v1 = *(const float4*)(src + i + 4);
    __half2 h0 = __floats2half2_rn(v0.x, v0.y), h1 = __floats2half2_rn(v0.z, v0.w);
    __half2 h2 = __floats2half2_rn(v1.x, v1.y), h3 = __floats2half2_rn(v1.z, v1.w);
    uint4 w = make_uint4(*(unsigned*)&h0, *(unsigned*)&h1, *(unsigned*)&h2, *(unsigned*)&h3);
    *(uint4*)(dst + i) = w;
}

__device__ __forceinline__ void mma_h(float* c, const unsigned* a, const unsigned* b) {
    asm volatile(
        "mma.sync.aligned.m16n8k16.row.col.f32.f16.f16.f32 "
        "{%0,%1,%2,%3},{%4,%5,%6,%7},{%8,%9},{%0,%1,%2,%3};"
        : "+f"(c[0]), "+f"(c[1]), "+f"(c[2]), "+f"(c[3])
        : "r"(a[0]), "r"(a[1]), "r"(a[2]), "r"(a[3]), "r"(b[0]), "r"(b[1]));
}
__device__ __forceinline__ void cp16(unsigned dst, const void* src) {
    asm volatile("cp.async.cg.shared.global [%0], [%1], 16;" :: "r"(dst), "l"(src));
}
#define CP_COMMIT() asm volatile("cp.async.commit_group;")
#define CP_WAIT2()  asm volatile("cp.async.wait_group 2;")
#define LDSM4(r0, r1, r2, r3, addr)                                             \
    asm volatile("ldmatrix.sync.aligned.m8n8.x4.shared.b16 {%0,%1,%2,%3}, [%4];" \
        : "=r"(r0), "=r"(r1), "=r"(r2), "=r"(r3) : "r"(addr))
#define LDSM4T(r0, r1, r2, r3, addr)                                            \
    asm volatile("ldmatrix.sync.aligned.m8n8.x4.trans.shared.b16 {%0,%1,%2,%3}, [%4];" \
        : "=r"(r0), "=r"(r1), "=r"(r2), "=r"(r3) : "r"(addr))

// shared GEMM mainloop body: warp tile 64m x 64n, CTA 128m x 256n
// acc[4][8][4]; aLd/bLd precomputed ldmatrix bases
#define GEMM_CHUNK(stOff)                                                       \
    _Pragma("unroll")                                                           \
    for (int kk = 0; kk < 2; kk++) {                                            \
        unsigned af[4][4];                                                      \
        _Pragma("unroll")                                                       \
        for (int mi = 0; mi < 4; mi++)                                          \
            LDSM4(af[mi][0], af[mi][1], af[mi][2], af[mi][3],                   \
                  aLd + (stOff) + mi * (16 * STRA * 2) + kk * 32);              \
        _Pragma("unroll")                                                       \
        for (int p = 0; p < 4; p++) {                                           \
            unsigned b0, b1, b2, b3;                                            \
            LDSM4T(b0, b1, b2, b3,                                              \
                   bLd + (stOff) + kk * (16 * BSTR * 2) + p * 32);              \
            unsigned bf0[2] = { b0, b1 }, bf1[2] = { b2, b3 };                  \
            _Pragma("unroll")                                                   \
            for (int mi = 0; mi < 4; mi++) {                                    \
                mma_h(acc[mi][2 * p],     af[mi], bf0);                         \
                mma_h(acc[mi][2 * p + 1], af[mi], bf1);                         \
            }                                                                   \
        }                                                                       \
    }

// ============== fused gate/up + silu: CTA 128m x (128g + 128u) ==============
__global__ __launch_bounds__(256, 1)
void k_mlp()
{
    extern __shared__ __half smh[];
    int e   = blockIdx.z;
    int cnt = cnt_d[e];
    int m0  = blockIdx.y * BM;
    if (m0 >= cnt) return;
    int n0    = blockIdx.x * 128;           // per-matrix n offset
    int valid = min(cnt - m0, BM);
    int pbase = base_d[e] + m0;
    int tid = threadIdx.x, lane = tid & 31, wid = tid >> 5;

    int* toks = (int*)((char*)smh + TOKS_OFF_F);
    if (tid < BM) toks[tid] = perm_d[pbase + min(tid, valid - 1)];
    __syncthreads();

    // A staging: 2 thr/row, 16 halfs (2 cp16)... -> wait: 16 halfs=32B=2 cp16
    int arow = tid >> 1, aseg = tid & 1;
    const __half* Ag = x_h + (size_t)toks[arow] * HID + aseg * 16;
    unsigned sb = (unsigned)__cvta_generic_to_shared(smh);
    unsigned aD = sb + (arow * STRA + aseg * 16) * 2;

    // B staging: 32 k-rows x 256 combined cols; thread -> (k-row, 32-col seg)
    int brw = tid >> 3, bsg = tid & 7;
    int ccol = bsg * 32;                    // combined col 0..255
    const __half* Bg = (ccol < 128 ? gw_h : uw_h) + (size_t)e * HID * IEXP
                     + (size_t)brw * IEXP + n0 + (ccol & 127);
    unsigned bD = sb + (AH + brw * BSTR + ccol) * 2;

    auto stage = [&](int s, int k0) {
        unsigned off = (unsigned)s * (STGH * 2);
        const __half* as = Ag + k0;
        cp16(aD + off, as);
        cp16(aD + off + 16, as + 8);
        const __half* bs = Bg + (size_t)k0 * IEXP;
#pragma unroll
        for (int j = 0; j < 4; j++) cp16(bD + off + j * 16, bs + j * 8);
    };

    float acc[4][8][4];
#pragma unroll
    for (int i = 0; i < 4; i++)
#pragma unroll
        for (int j = 0; j < 8; j++)
#pragma unroll
            for (int k = 0; k < 4; k++) acc[i][j][k] = 0.f;

    int wm = (wid & 1) * 64;                // 2 m-positions
    int wn = (wid >> 1) * 64;               // 4 n-positions over combined 256

    unsigned aLd = sb + ((wm + (lane & 7) + ((lane >> 3) & 1) * 8) * STRA
                         + ((lane >> 4) & 1) * 8) * 2;
    unsigned bLd = sb + (AH + ((lane & 7) + ((lane >> 3) & 1) * 8) * BSTR
                         + wn + ((lane >> 4) & 1) * 8) * 2;

    stage(0, 0);      CP_COMMIT();
    stage(1, BK);     CP_COMMIT();
    stage(2, 2 * BK); CP_COMMIT();

    const int nch = HID / BK;               // 64
    int s = 0;
    for (int i = 0; i < nch; i++) {
        CP_WAIT2();
        __syncthreads();
        {
            int s3 = s + 3; if (s3 >= NST) s3 -= NST;
            if (i + 3 < nch) stage(s3, (i + 3) * BK);
        }
        CP_COMMIT();
        unsigned stOff = (unsigned)s * (STGH * 2);
        GEMM_CHUNK(stOff)
        s = (s + 1 == NST) ? 0 : s + 1;
    }
    __syncthreads();

    // ---- exchange + silu: combined cols <128 are gate, >=128 are up ----
    float* HSg = (float*)smh;                       // [128][HSW]
    float* HSu = (float*)smh + BM * HSW;
    {
        int isUp = (wn >= 128);
        int nloc = wn & 127;
        float* HS = isUp ? HSu : HSg;
#pragma unroll
        for (int mi = 0; mi < 4; mi++) {
            int rb = wm + mi * 16 + (lane >> 2);
#pragma unroll
            for (int ni = 0; ni < 8; ni++) {
                int cc = nloc + ni * 8 + (lane & 3) * 2;
                HS[rb * HSW + cc]           = acc[mi][ni][0];
                HS[rb * HSW + cc + 1]       = acc[mi][ni][1];
                HS[(rb + 8) * HSW + cc]     = acc[mi][ni][2];
                HS[(rb + 8) * HSW + cc + 1] = acc[mi][ni][3];
            }
        }
    }
    __syncthreads();
    {
        int r = tid >> 1, hf = tid & 1;             // 64 cols per thread
        if (r < valid) {
            const float* g = HSg + r * HSW + hf * 64;
            const float* u = HSu + r * HSW + hf * 64;
            __half* dst = h_h + (size_t)(pbase + r) * IEXP + n0 + hf * 64;
#pragma unroll
            for (int j = 0; j < 64; j += 8) {
                float hv[8];
#pragma unroll
                for (int q = 0; q < 8; q++) {
                    float gv = g[j + q], uv = u[j + q];
                    hv[q] = gv / (1.f + __expf(-gv)) * uv;
                }
                __half2 p0 = __floats2half2_rn(hv[0], hv[1]);
                __half2 p1 = __floats2half2_rn(hv[2], hv[3]);
                __half2 p2 = __floats2half2_rn(hv[4], hv[5]);
                __half2 p3 = __floats2half2_rn(hv[6], hv[7]);
                uint4 w = make_uint4(*(unsigned*)&p0, *(unsigned*)&p1,
                                     *(unsigned*)&p2, *(unsigned*)&p3);
                *(uint4*)(dst + j) = w;
            }
        }
    }
}

// ============== down-proj: CTA 128m x 256n, row scatter ======================
__global__ __launch_bounds__(256, 1)
void k_down(float* __restrict__ out)
{
    extern __shared__ __half smh[];
    int e   = blockIdx.z;
    int cnt = cnt_d[e];
    int m0  = blockIdx.y * BM;
    if (m0 >= cnt) return;
    int n0    = blockIdx.x * 256;
    int valid = min(cnt - m0, BM);
    int pbase = base_d[e] + m0;
    int tid = threadIdx.x, lane = tid & 31, wid = tid >> 5;

    int* toks = (int*)((char*)smh + TOKS_OFF_D);
    if (tid < BM) toks[tid] = perm_d[pbase + min(tid, valid - 1)];
    __syncthreads();

    int arow = tid >> 1, aseg = tid & 1;
    const __half* Ag = h_h + (size_t)(pbase + min(arow, valid - 1)) * IEXP + aseg * 16;
    unsigned sb = (unsigned)__cvta_generic_to_shared(smh);
    unsigned aD = sb + (arow * STRA + aseg * 16) * 2;

    int brw = tid >> 3, bsg = tid & 7;
    const __half* Dg = dw_h + (size_t)e * IEXP * HID + (size_t)brw * HID + n0 + bsg * 32;
    unsigned bD = sb + (AH + brw * BSTR + bsg * 32) * 2;

    auto stage = [&](int s, int k0) {
        unsigned off = (unsigned)s * (STGH * 2);
        const __half* as = Ag + k0;
        cp16(aD + off, as);
        cp16(aD + off + 16, as + 8);
        const __half* bs = Dg + (size_t)k0 * HID;
#pragma unroll
        for (int j = 0; j < 4; j++) cp16(bD + off + j * 16, bs + j * 8);
    };

    float acc[4][8][4];
#pragma unroll
    for (int i = 0; i < 4; i++)
#pragma unroll
        for (int j = 0; j < 8; j++)
#pragma unroll
            for (int k = 0; k < 4; k++) acc[i][j][k] = 0.f;

    int wm = (wid & 1) * 64;
    int wn = (wid >> 1) * 64;

    unsigned aLd = sb + ((wm + (lane & 7) + ((lane >> 3) & 1) * 8) * STRA
                         + ((lane >> 4) & 1) * 8) * 2;
    unsigned bLd = sb + (AH + ((lane & 7) + ((lane >> 3) & 1) * 8) * BSTR
                         + wn + ((lane >> 4) & 1) * 8) * 2;

    stage(0, 0);      CP_COMMIT();
    stage(1, BK);     CP_COMMIT();
    stage(2, 2 * BK); CP_COMMIT();

    const int nch = IEXP / BK;              // 32
    int s = 0;
    for (int i = 0; i < nch; i++) {
        CP_WAIT2();
        __syncthreads();
        {
            int s3 = s + 3; if (s3 >= NST) s3 -= NST;
            if (i + 3 < nch) stage(s3, (i + 3) * BK);
        }
        CP_COMMIT();
        unsigned stOff = (unsigned)s * (STGH * 2);
        GEMM_CHUNK(stOff)
        s = (s + 1 == NST) ? 0 : s + 1;
    }

    // scatter rows by token id
#pragma unroll
    for (int mi = 0; mi < 4; mi++) {
        int rb = wm + mi * 16 + (lane >> 2);
#pragma unroll
        for (int ni = 0; ni < 8; ni++) {
            int cc = n0 + wn + ni * 8 + (lane & 3) * 2;
#pragma unroll
            for (int h = 0; h < 2; h++) {
                int r = rb + h * 8;
                if (r < valid) {
                    float* row = out + (size_t)toks[r] * HID;
                    row[cc]     = acc[mi][ni][h * 2];
                    row[cc + 1] = acc[mi][ni][h * 2 + 1];
                }
            }
        }
    }
}

extern "C" void kernel_launch(void* const* d_in, const int* in_sizes, int n_in,
                              void* d_out, int out_size)
{
    const float* hs   = (const float*)d_in[0];
    const int*   ids  = (const int*)d_in[1];
    const float* gate = (const float*)d_in[2];
    const float* up   = (const float*)d_in[3];
    const float* down = (const float*)d_in[4];
    float*       out  = (float*)d_out;

    cudaFuncSetAttribute(k_mlp,  cudaFuncAttributeMaxDynamicSharedMemorySize, SMB_F);
    cudaFuncSetAttribute(k_down, cudaFuncAttributeMaxDynamicSharedMemorySize, SMB_D);

    k_route<<<1, 256>>>(ids);
    k_prep<<<(T_TOK * HID) / 2048, 256>>>(hs);
    k_wconv<<<dim3((NEXP * HID * IEXP) / 2048, 3), 256>>>(gate, up, down);
    k_mlp <<<dim3(IEXP / 128, T_TOK / BM, NEXP), 256, SMB_F>>>();
    k_down<<<dim3(HID / 256,  T_TOK / BM, NEXP), 256, SMB_D>>>(out);
}

// round 16
// speedup vs baseline: 1.3284x; 1.1961x over previous
#include <cuda_runtime.h>
#include <cuda_fp16.h>
#include <cstdint>

#define T_TOK 16384
#define HID   2048
#define IEXP  1024
#define NEXP  8
#define VOCAB_SZ 100000
#define TPE   12500

#define BM 128
#define BK 32
#define STRA 40                       // A smem row stride (halfs): 80B, aligned + conflict-free
#define AH (BM * STRA)                // 5120 halfs / stage

#define BSTRF 72
#define BHF (2 * BK * BSTRF)          // 4608 halfs
#define STGH_F (AH + BHF)             // 9728 halfs / stage
#define NST 5
#define SMB_F (NST * STGH_F * 2 + 576)   // 97856 B -> 2 CTAs/SM

#define BSTRD 136
#define BHD (BK * BSTRD)              // 4352 halfs
#define STGH_D (AH + BHD)             // 9472 halfs
#define SMB_D (NST * STGH_D * 2 + 576)   // 95296 B -> 2 CTAs/SM

__device__ __half x_h [(size_t)T_TOK * HID];
__device__ __half h_h [(size_t)T_TOK * IEXP];
__device__ __half gw_h[(size_t)NEXP * HID * IEXP];
__device__ __half uw_h[(size_t)NEXP * HID * IEXP];
__device__ __half dw_h[(size_t)NEXP * IEXP * HID];
__device__ int    perm_d[T_TOK];
__device__ int    cnt_d[NEXP];
__device__ int    base_d[NEXP];

__global__ void k_route(const int* __restrict__ ids) {
    __shared__ int c[NEXP], b[NEXP], cu[NEXP];
    int t = threadIdx.x;
    if (t < NEXP) { c[t] = 0; cu[t] = 0; }
    __syncthreads();
    for (int i = t; i < T_TOK; i += 256) {
        int v = ids[i]; v = max(0, min(v, VOCAB_SZ - 1));
        atomicAdd(&c[min(v / TPE, NEXP - 1)], 1);
    }
    __syncthreads();
    if (t == 0) { int s = 0; for (int e = 0; e < NEXP; e++) { b[e] = s; s += c[e]; } }
    __syncthreads();
    for (int i = t; i < T_TOK; i += 256) {
        int v = ids[i]; v = max(0, min(v, VOCAB_SZ - 1));
        int e = min(v / TPE, NEXP - 1);
        perm_d[b[e] + atomicAdd(&cu[e], 1)] = i;
    }
    if (t < NEXP) { cnt_d[t] = c[t]; base_d[t] = b[t]; }
}

__global__ void k_prep(const float* __restrict__ X) {
    size_t i = ((size_t)blockIdx.x * blockDim.x + threadIdx.x) * 8;
    float4 v0 = *(const float4*)(X + i);
    float4 v1 = *(const float4*)(X + i + 4);
    __half2 h0 = __floats2half2_rn(v0.x, v0.y), h1 = __floats2half2_rn(v0.z, v0.w);
    __half2 h2 = __floats2half2_rn(v1.x, v1.y), h3 = __floats2half2_rn(v1.z, v1.w);
    uint4 w = make_uint4(*(unsigned*)&h0, *(unsigned*)&h1, *(unsigned*)&h2, *(unsigned*)&h3);
    *(uint4*)(x_h + i) = w;
}

__global__ void k_wconv(const float* __restrict__ G, const float* __restrict__ U,
                        const float* __restrict__ D) {
    const float* src = (blockIdx.y == 0) ? G : (blockIdx.y == 1) ? U : D;
    __half* dst = (blockIdx.y == 0) ? gw_h : (blockIdx.y == 1) ? uw_h : dw_h;
    size_t i = ((size_t)blockIdx.x * blockDim.x + threadIdx.x) * 8;
    float4 v0 = *(const float4*)(src + i);
    float4 v1 = *(const float4*)(src + i + 4);
    __half2 h0 = __floats2half2_rn(v0.x, v0.y), h1 = __floats2half2_rn(v0.z, v0.w);
    __half2 h2 = __floats2half2_rn(v1.x, v1.y), h3 = __floats2half2_rn(v1.z, v1.w);
    uint4 w = make_uint4(*(unsigned*)&h0, *(unsigned*)&h1, *(unsigned*)&h2, *(unsigned*)&h3);
    *(uint4*)(dst + i) = w;
}

__device__ __forceinline__ void mma_h(float* c, const unsigned* a, const unsigned* b) {
    asm volatile(
        "mma.sync.aligned.m16n8k16.row.col.f32.f16.f16.f32 "
        "{%0,%1,%2,%3},{%4,%5,%6,%7},{%8,%9},{%0,%1,%2,%3};"
        : "+f"(c[0]), "+f"(c[1]), "+f"(c[2]), "+f"(c[3])
        : "r"(a[0]), "r"(a[1]), "r"(a[2]), "r"(a[3]), "r"(b[0]), "r"(b[1]));
}
__device__ __forceinline__ void cp16(unsigned dst, const void* src) {
    asm volatile("cp.async.cg.shared.global [%0], [%1], 16;" :: "r"(dst), "l"(src));
}
#define CP_COMMIT() asm volatile("cp.async.commit_group;")
#define CP_WAIT3()  asm volatile("cp.async.wait_group 3;")
#define LDSM4(r0, r1, r2, r3, addr)                                             \
    asm volatile("ldmatrix.sync.aligned.m8n8.x4.shared.b16 {%0,%1,%2,%3}, [%4];" \
        : "=r"(r0), "=r"(r1), "=r"(r2), "=r"(r3) : "r"(addr))
#define LDSM4T(r0, r1, r2, r3, addr)                                            \
    asm volatile("ldmatrix.sync.aligned.m8n8.x4.trans.shared.b16 {%0,%1,%2,%3}, [%4];" \
        : "=r"(r0), "=r"(r1), "=r"(r2), "=r"(r3) : "r"(addr))

// ================= fused gate/up + silu (CTA 128m x 64n, both matrices) =====
__global__ __launch_bounds__(256, 2)
void k_mlp()
{
    extern __shared__ __half smh[];
    int e   = blockIdx.z;
    int cnt = cnt_d[e];
    int m0  = blockIdx.y * BM;
    if (m0 >= cnt) return;
    int n0    = blockIdx.x * 64;
    int valid = min(cnt - m0, BM);
    int pbase = base_d[e] + m0;
    int tid = threadIdx.x, lane = tid & 31, wid = tid >> 5;

    int* toks = (int*)(smh + NST * STGH_F);
    if (tid < BM) toks[tid] = perm_d[pbase + min(tid, valid - 1)];
    __syncthreads();

    // A staging: 2 thr/row, 16 halfs (32B) each
    int arow = tid >> 1, aseg = tid & 1;
    const __half* Ag = x_h + (size_t)toks[arow] * HID + aseg * 16;
    unsigned sb = (unsigned)__cvta_generic_to_shared(smh);
    unsigned aD = sb + (arow * STRA + aseg * 16) * 2;

    // B staging: [k][n] half; 32 k-rows x 64 halfs per matrix; 8 thr/row x 16B
    int brow = tid >> 3, bslot = tid & 7;
    const __half* Gg = gw_h + (size_t)e * HID * IEXP + (size_t)brow * IEXP + n0 + bslot * 8;
    const __half* Ug = uw_h + (size_t)e * HID * IEXP + (size_t)brow * IEXP + n0 + bslot * 8;
    unsigned gD = sb + (AH + brow * BSTRF + bslot * 8) * 2;
    unsigned uD = sb + (AH + BK * BSTRF + brow * BSTRF + bslot * 8) * 2;

    auto stage = [&](int s, int k0) {
        unsigned off = (unsigned)s * (STGH_F * 2);
        cp16(aD + off,      Ag + k0);
        cp16(aD + off + 16, Ag + k0 + 8);
        cp16(gD + off, Gg + (size_t)k0 * IEXP);
        cp16(uD + off, Ug + (size_t)k0 * IEXP);
    };

    float acc[2][8][4];
#pragma unroll
    for (int i = 0; i < 2; i++)
#pragma unroll
        for (int j = 0; j < 8; j++)
#pragma unroll
            for (int k = 0; k < 4; k++) acc[i][j][k] = 0.f;

    int sel = wid >> 2;                  // 0: gate, 1: up
    int wm  = (wid & 3) * 32;

    unsigned aLd = sb + ((wm + (lane & 7) + ((lane >> 3) & 1) * 8) * STRA
                         + ((lane >> 4) & 1) * 8) * 2;
    unsigned bLd = sb + (AH + sel * (BK * BSTRF)
                         + ((lane & 7) + ((lane >> 3) & 1) * 8) * BSTRF
                         + ((lane >> 4) & 1) * 8) * 2;

    stage(0, 0);       CP_COMMIT();
    stage(1, BK);      CP_COMMIT();
    stage(2, 2 * BK);  CP_COMMIT();
    stage(3, 3 * BK);  CP_COMMIT();

    const int nch = HID / BK;            // 64
    int s = 0;
    for (int i = 0; i < nch; i++) {
        CP_WAIT3();
        __syncthreads();
        {
            int s4 = s + 4; if (s4 >= NST) s4 -= NST;
            if (i + 4 < nch) stage(s4, (i + 4) * BK);
        }
        CP_COMMIT();

        unsigned stOff = (unsigned)s * (STGH_F * 2);
#pragma unroll
        for (int kk = 0; kk < 2; kk++) {
            unsigned af[2][4];
#pragma unroll
            for (int mi = 0; mi < 2; mi++)
                LDSM4(af[mi][0], af[mi][1], af[mi][2], af[mi][3],
                      aLd + stOff + mi * (16 * STRA * 2) + kk * 32);
#pragma unroll
            for (int p = 0; p < 4; p++) {
                unsigned b0, b1, b2, b3;
                LDSM4T(b0, b1, b2, b3,
                       bLd + stOff + kk * (16 * BSTRF * 2) + p * 32);
                unsigned bf0[2] = { b0, b1 }, bf1[2] = { b2, b3 };
#pragma unroll
                for (int mi = 0; mi < 2; mi++) {
                    mma_h(acc[mi][2 * p],     af[mi], bf0);
                    mma_h(acc[mi][2 * p + 1], af[mi], bf1);
                }
            }
        }
        s = (s + 1 == NST) ? 0 : s + 1;
    }
    __syncthreads();

    // ---- exchange + silu ----
    float* HS = (float*)smh + sel * (BM * 68);
#pragma unroll
    for (int mi = 0; mi < 2; mi++) {
        int rb = wm + mi * 16 + (lane >> 2);
#pragma unroll
        for (int ni = 0; ni < 8; ni++) {
            int cc = ni * 8 + (lane & 3) * 2;
            HS[rb * 68 + cc]           = acc[mi][ni][0];
            HS[rb * 68 + cc + 1]       = acc[mi][ni][1];
            HS[(rb + 8) * 68 + cc]     = acc[mi][ni][2];
            HS[(rb + 8) * 68 + cc + 1] = acc[mi][ni][3];
        }
    }
    __syncthreads();
    {
        int r = tid >> 1, hf = tid & 1;
        if (r < valid) {
            const float* g = (float*)smh + r * 68 + hf * 32;
            const float* u = (float*)smh + BM * 68 + r * 68 + hf * 32;
            __half* dst = h_h + (size_t)(pbase + r) * IEXP + n0 + hf * 32;
#pragma unroll
            for (int j = 0; j < 32; j += 8) {
                float hv[8];
#pragma unroll
                for (int q = 0; q < 8; q++) {
                    float gv = g[j + q], uv = u[j + q];
                    hv[q] = gv / (1.f + __expf(-gv)) * uv;
                }
                __half2 p0 = __floats2half2_rn(hv[0], hv[1]);
                __half2 p1 = __floats2half2_rn(hv[2], hv[3]);
                __half2 p2 = __floats2half2_rn(hv[4], hv[5]);
                __half2 p3 = __floats2half2_rn(hv[6], hv[7]);
                uint4 w = make_uint4(*(unsigned*)&p0, *(unsigned*)&p1,
                                     *(unsigned*)&p2, *(unsigned*)&p3);
                *(uint4*)(dst + j) = w;
            }
        }
    }
}

// ================= down-proj (CTA 128m x 128n) with row scatter ==============
__global__ __launch_bounds__(256, 2)
void k_down(float* __restrict__ out)
{
    extern __shared__ __half smh[];
    int e   = blockIdx.z;
    int cnt = cnt_d[e];
    int m0  = blockIdx.y * BM;
    if (m0 >= cnt) return;
    int n0    = blockIdx.x * 128;
    int valid = min(cnt - m0, BM);
    int pbase = base_d[e] + m0;
    int tid = threadIdx.x, lane = tid & 31, wid = tid >> 5;

    int* toks = (int*)(smh + NST * STGH_D);
    if (tid < BM) toks[tid] = perm_d[pbase + min(tid, valid - 1)];
    __syncthreads();

    int arow = tid >> 1, aseg = tid & 1;
    const __half* Ag = h_h + (size_t)(pbase + min(arow, valid - 1)) * IEXP + aseg * 16;
    unsigned sb = (unsigned)__cvta_generic_to_shared(smh);
    unsigned aD = sb + (arow * STRA + aseg * 16) * 2;

    // B: 32 k-rows x 128 halfs (256B): 16 thr/row x 16B
    int brow = tid >> 4, bslot = tid & 15;
    const __half* Dg = dw_h + (size_t)e * IEXP * HID + (size_t)brow * HID + n0 + bslot * 8;
    unsigned bD = sb + (AH + brow * BSTRD + bslot * 8) * 2;

    auto stage = [&](int s, int k0) {
        unsigned off = (unsigned)s * (STGH_D * 2);
        cp16(aD + off,      Ag + k0);
        cp16(aD + off + 16, Ag + k0 + 8);
        cp16(bD + off, Dg + (size_t)k0 * HID);
        cp16(bD + off + (16 * BSTRD * 2), Dg + (size_t)(k0 + 16) * HID);
    };

    float acc[2][8][4];
#pragma unroll
    for (int i = 0; i < 2; i++)
#pragma unroll
        for (int j = 0; j < 8; j++)
#pragma unroll
            for (int k = 0; k < 4; k++) acc[i][j][k] = 0.f;

    int wm = (wid & 3) * 32;
    int wn = (wid >> 2) * 64;

    unsigned aLd = sb + ((wm + (lane & 7) + ((lane >> 3) & 1) * 8) * STRA
                         + ((lane >> 4) & 1) * 8) * 2;
    unsigned bLd = sb + (AH + ((lane & 7) + ((lane >> 3) & 1) * 8) * BSTRD
                         + wn + ((lane >> 4) & 1) * 8) * 2;

    stage(0, 0);       CP_COMMIT();
    stage(1, BK);      CP_COMMIT();
    stage(2, 2 * BK);  CP_COMMIT();
    stage(3, 3 * BK);  CP_COMMIT();

    const int nch = IEXP / BK;           // 32
    int s = 0;
    for (int i = 0; i < nch; i++) {
        CP_WAIT3();
        __syncthreads();
        {
            int s4 = s + 4; if (s4 >= NST) s4 -= NST;
            if (i + 4 < nch) stage(s4, (i + 4) * BK);
        }
        CP_COMMIT();

        unsigned stOff = (unsigned)s * (STGH_D * 2);
#pragma unroll
        for (int kk = 0; kk < 2; kk++) {
            unsigned af[2][4];
#pragma unroll
            for (int mi = 0; mi < 2; mi++)
                LDSM4(af[mi][0], af[mi][1], af[mi][2], af[mi][3],
                      aLd + stOff + mi * (16 * STRA * 2) + kk * 32);
#pragma unroll
            for (int p = 0; p < 4; p++) {
                unsigned b0, b1, b2, b3;
                LDSM4T(b0, b1, b2, b3,
                       bLd + stOff + kk * (16 * BSTRD * 2) + p * 32);
                unsigned bf0[2] = { b0, b1 }, bf1[2] = { b2, b3 };
#pragma unroll
                for (int mi = 0; mi < 2; mi++) {
                    mma_h(acc[mi][2 * p],     af[mi], bf0);
                    mma_h(acc[mi][2 * p + 1], af[mi], bf1);
                }
            }
        }
        s = (s + 1 == NST) ? 0 : s + 1;
    }

    // scatter rows by token id
#pragma unroll
    for (int mi = 0; mi < 2; mi++) {
        int rb = wm + mi * 16 + (lane >> 2);
#pragma unroll
        for (int ni = 0; ni < 8; ni++) {
            int cc = n0 + wn + ni * 8 + (lane & 3) * 2;
#pragma unroll
            for (int h = 0; h < 2; h++) {
                int r = rb + h * 8;
                if (r < valid) {
                    float* row = out + (size_t)toks[r] * HID;
                    row[cc]     = acc[mi][ni][h * 2];
                    row[cc + 1] = acc[mi][ni][h * 2 + 1];
                }
            }
        }
    }
}

extern "C" void kernel_launch(void* const* d_in, const int* in_sizes, int n_in,
                              void* d_out, int out_size)
{
    const float* hs   = (const float*)d_in[0];
    const int*   ids  = (const int*)d_in[1];
    const float* gate = (const float*)d_in[2];
    const float* up   = (const float*)d_in[3];
    const float* down = (const float*)d_in[4];
    float*       out  = (float*)d_out;

    cudaFuncSetAttribute(k_mlp,  cudaFuncAttributeMaxDynamicSharedMemorySize, SMB_F);
    cudaFuncSetAttribute(k_down, cudaFuncAttributeMaxDynamicSharedMemorySize, SMB_D);

    k_route<<<1, 256>>>(ids);
    k_prep<<<(T_TOK * HID) / 2048, 256>>>(hs);
    k_wconv<<<dim3((NEXP * HID * IEXP) / 2048, 3), 256>>>(gate, up, down);
    k_mlp <<<dim3(IEXP / 64, 32, NEXP), 256, SMB_F>>>();
    k_down<<<dim3(HID / 128, 32, NEXP), 256, SMB_D>>>(out);
}